// round 12
// baseline (speedup 1.0000x reference)
#include <cuda_runtime.h>
#include <cuda_fp16.h>
#include <mma.h>
#include <math.h>

using namespace nvcuda;

#define HEADS 8
#define OUTF 32
#define HF 256
#define IN_FEATS 256
#define NEG_SLOPE 0.2f
#define SCAN_CHUNK 4096
#define N_NODES_MAX 100000
#define N_EDGES_MAX 3200000
#define FULL 0xffffffffu

// ---------------- device scratch ----------------
__device__ __align__(16) __half g_hh[(size_t)N_NODES_MAX * HF];   // projected features, fp16
__device__ __align__(16) __half g_w_h[HF * IN_FEATS];             // weights fp16
__device__ float g_el[N_NODES_MAX * HEADS];
__device__ float g_er[N_NODES_MAX * HEADS];
__device__ int   g_cnt[N_NODES_MAX];
__device__ int   g_row_off[N_NODES_MAX + 1];
__device__ int   g_cursor[N_NODES_MAX];
__device__ int   g_csr_src[N_EDGES_MAX];
__device__ int   g_blksum[64];
__device__ int   g_blkoff[64];

// ---------------- fp32 -> fp16 weight converter (256 KB, ~2 us) ----------------
__global__ void cvt_w_kernel(const float* __restrict__ W) {
    int i = blockIdx.x * blockDim.x + threadIdx.x;   // HF*IN_FEATS/8 = 8192
    const float4* p = (const float4*)(W + (size_t)i * 8);
    float4 a = p[0], b = p[1];
    __half2 h0 = __floats2half2_rn(a.x, a.y);
    __half2 h1 = __floats2half2_rn(a.z, a.w);
    __half2 h2 = __floats2half2_rn(b.x, b.y);
    __half2 h3 = __floats2half2_rn(b.z, b.w);
    uint4 pk;
    pk.x = *(unsigned*)&h0; pk.y = *(unsigned*)&h1;
    pk.z = *(unsigned*)&h2; pk.w = *(unsigned*)&h3;
    *(uint4*)(g_w_h + (size_t)i * 8) = pk;
}

// ---------------- 1) HMMA GEMM (BM=64, BN=256, BK=32) + fused conversion + epilogue ----------------
// feat read ONCE as fp32, converted to fp16 in registers. Warp grid 2(m) x 4(n);
// warp tile 32x64 = 2x4 wmma 16x16x16 fragments (fp32 accum).
// Epilogue: per-warp smem stage -> fp16 h store + exact el/er (warp's 64 cols = 2 heads).
#define GEMM_SMEM_BYTES 73728   // max(2*(64+256)*40*2 = 51200 staging, 8*32*72*4 = 73728 epilogue)

__global__ void __launch_bounds__(256) gemm_wmma_kernel(const float* __restrict__ feat,
                                                        const float* __restrict__ attn_l,
                                                        const float* __restrict__ attn_r,
                                                        int M) {
    extern __shared__ char dynsmem[];
    __half* As = (__half*)dynsmem;            // [2][64][40]
    __half* Bs = As + 2 * 64 * 40;            // [2][256][40]
    float*  epi = (float*)dynsmem;            // reuse: [8][32][72]
    __shared__ float al_s[256], ar_s[256];

    const int m0 = blockIdx.x * 64;
    const int tid = threadIdx.x;
    const int warp = tid >> 5;
    const int lane = tid & 31;
    const int wy = warp >> 2;   // 0..1 (m)
    const int wx = warp & 3;    // 0..3 (n)

    if (tid < 256) {
        al_s[tid] = attn_l[tid];
        ar_s[tid] = attn_r[tid];
    }

    // A loader: 256 chunks (64 rows x 4 chunks of 8 cols); 1 per thread; fp32->fp16
    const int ar_r = tid >> 2, ar_q = tid & 3;
    // B loader: 1024 chunks (256 rows x 4 chunks of 8 halves); 4 per thread
    uint4 aPk, bPk[4];

    auto load_a = [&](int k0) {
        int grow = m0 + ar_r;
        if (grow < M) {
            const float4* p = (const float4*)(feat + (size_t)grow * IN_FEATS + k0 + ar_q * 8);
            float4 x = p[0], y = p[1];
            __half2 h0 = __floats2half2_rn(x.x, x.y);
            __half2 h1 = __floats2half2_rn(x.z, x.w);
            __half2 h2 = __floats2half2_rn(y.x, y.y);
            __half2 h3 = __floats2half2_rn(y.z, y.w);
            aPk.x = *(unsigned*)&h0; aPk.y = *(unsigned*)&h1;
            aPk.z = *(unsigned*)&h2; aPk.w = *(unsigned*)&h3;
        } else {
            aPk = make_uint4(0, 0, 0, 0);
        }
    };
    auto load_b = [&](int k0) {
#pragma unroll
        for (int t = 0; t < 4; t++) {
            int idx = tid + 256 * t;
            int r = idx >> 2, q = idx & 3;
            bPk[t] = *(const uint4*)(g_w_h + (size_t)r * IN_FEATS + k0 + q * 8);
        }
    };
    auto commit = [&](int buf) {
        *(uint4*)(As + buf * 64 * 40 + ar_r * 40 + ar_q * 8) = aPk;
#pragma unroll
        for (int t = 0; t < 4; t++) {
            int idx = tid + 256 * t;
            int r = idx >> 2, q = idx & 3;
            *(uint4*)(Bs + buf * 256 * 40 + r * 40 + q * 8) = bPk[t];
        }
    };

    load_a(0); load_b(0); commit(0);
    __syncthreads();

    wmma::fragment<wmma::accumulator, 16, 16, 16, float> acc[2][4];
#pragma unroll
    for (int i = 0; i < 2; i++)
#pragma unroll
        for (int j = 0; j < 4; j++) wmma::fill_fragment(acc[i][j], 0.0f);

    int p = 0;
#pragma unroll 1
    for (int k0 = 0; k0 < IN_FEATS; k0 += 32) {
        const bool more = (k0 + 32 < IN_FEATS);
        if (more) { load_a(k0 + 32); load_b(k0 + 32); }

        const __half* Ab = As + p * 64 * 40;
        const __half* Bb = Bs + p * 256 * 40;
#pragma unroll
        for (int ks = 0; ks < 32; ks += 16) {
            wmma::fragment<wmma::matrix_a, 16, 16, 16, __half, wmma::row_major> fa[2];
            wmma::fragment<wmma::matrix_b, 16, 16, 16, __half, wmma::col_major> fb[4];
#pragma unroll
            for (int i = 0; i < 2; i++)
                wmma::load_matrix_sync(fa[i], Ab + (wy * 32 + i * 16) * 40 + ks, 40);
#pragma unroll
            for (int j = 0; j < 4; j++)
                wmma::load_matrix_sync(fb[j], Bb + (wx * 64 + j * 16) * 40 + ks, 40);
#pragma unroll
            for (int i = 0; i < 2; i++)
#pragma unroll
                for (int j = 0; j < 4; j++)
                    wmma::mma_sync(acc[i][j], fa[i], fb[j], acc[i][j]);
        }

        if (more) {
            __syncthreads();
            p ^= 1;
            commit(p);
            __syncthreads();
        }
    }

    // all warps done with As/Bs before reusing the smem as epilogue staging
    __syncthreads();

    float* ws = epi + warp * 32 * 72;
#pragma unroll
    for (int i = 0; i < 2; i++)
#pragma unroll
        for (int j = 0; j < 4; j++)
            wmma::store_matrix_sync(ws + i * 16 * 72 + j * 16, acc[i][j], 72, wmma::mem_row_major);
    __syncwarp();

    const int grow = m0 + wy * 32 + lane;
    const float* al = al_s + wx * 64;
    const float* ar = ar_s + wx * 64;
    const float* hr = ws + lane * 72;

    float el0 = 0.f, er0 = 0.f, el1 = 0.f, er1 = 0.f;
#pragma unroll
    for (int c = 0; c < 32; c++) {
        float v = hr[c];
        el0 = fmaf(v, al[c], el0);
        er0 = fmaf(v, ar[c], er0);
    }
#pragma unroll
    for (int c = 32; c < 64; c++) {
        float v = hr[c];
        el1 = fmaf(v, al[c], el1);
        er1 = fmaf(v, ar[c], er1);
    }

    if (grow < M) {
        __half* hrow = g_hh + (size_t)grow * HF + wx * 64;
#pragma unroll
        for (int c8 = 0; c8 < 8; c8++) {
            __half2 h0 = __floats2half2_rn(hr[c8 * 8 + 0], hr[c8 * 8 + 1]);
            __half2 h1 = __floats2half2_rn(hr[c8 * 8 + 2], hr[c8 * 8 + 3]);
            __half2 h2 = __floats2half2_rn(hr[c8 * 8 + 4], hr[c8 * 8 + 5]);
            __half2 h3 = __floats2half2_rn(hr[c8 * 8 + 6], hr[c8 * 8 + 7]);
            uint4 pk;
            pk.x = *(unsigned*)&h0; pk.y = *(unsigned*)&h1;
            pk.z = *(unsigned*)&h2; pk.w = *(unsigned*)&h3;
            *(uint4*)(hrow + c8 * 8) = pk;
        }
        int hb = wx * 2;
        g_el[(size_t)grow * HEADS + hb] = el0;
        g_el[(size_t)grow * HEADS + hb + 1] = el1;
        g_er[(size_t)grow * HEADS + hb] = er0;
        g_er[(size_t)grow * HEADS + hb + 1] = er1;
    }
}

// ---------------- 2) CSR build ----------------
__global__ void zero_cnt_kernel(int N) {
    int i = blockIdx.x * blockDim.x + threadIdx.x;
    if (i < N) g_cnt[i] = 0;
}

__global__ void hist_kernel(const int* __restrict__ dst, int E) {
    int i = (blockIdx.x * blockDim.x + threadIdx.x) * 4;
    if (i + 4 <= E) {
        int4 d = __ldcs((const int4*)(dst + i));
        atomicAdd(&g_cnt[d.x], 1);
        atomicAdd(&g_cnt[d.y], 1);
        atomicAdd(&g_cnt[d.z], 1);
        atomicAdd(&g_cnt[d.w], 1);
    } else {
        for (int k = i; k < E; k++) atomicAdd(&g_cnt[dst[k]], 1);
    }
}

__global__ void __launch_bounds__(512) partial_sum_kernel(int N) {
    __shared__ int wsum[16];
    int b = blockIdx.x, tid = threadIdx.x;
    int base = b * SCAN_CHUNK + tid * 8;
    int s = 0;
    if (base + 8 <= N) {
        int4 a = *(const int4*)(g_cnt + base);
        int4 c = *(const int4*)(g_cnt + base + 4);
        s = a.x + a.y + a.z + a.w + c.x + c.y + c.z + c.w;
    } else {
#pragma unroll
        for (int k = 0; k < 8; k++) { int i = base + k; if (i < N) s += g_cnt[i]; }
    }
    int lane = tid & 31, wid = tid >> 5;
#pragma unroll
    for (int d = 16; d > 0; d >>= 1) s += __shfl_xor_sync(FULL, s, d);
    if (lane == 0) wsum[wid] = s;
    __syncthreads();
    if (wid == 0) {
        int w = (lane < 16) ? wsum[lane] : 0;
#pragma unroll
        for (int d = 16; d > 0; d >>= 1) w += __shfl_xor_sync(FULL, w, d);
        if (lane == 0) g_blksum[b] = w;
    }
}

__global__ void scan_blk_kernel(int nb, int E, int N) {
    int lane = threadIdx.x;
    int v = (lane < nb) ? g_blksum[lane] : 0;
    int x = v;
#pragma unroll
    for (int d = 1; d < 32; d <<= 1) {
        int y = __shfl_up_sync(FULL, x, d);
        if (lane >= d) x += y;
    }
    if (lane < nb) g_blkoff[lane] = x - v;
    if (lane == 0) g_row_off[N] = E;
}

__global__ void __launch_bounds__(512) scan_final_kernel(int N) {
    __shared__ int wsum[16];
    __shared__ int blk_base;
    int b = blockIdx.x, tid = threadIdx.x;
    int lane = tid & 31, wid = tid >> 5;
    if (tid == 0) blk_base = g_blkoff[b];

    int base = b * SCAN_CHUNK + tid * 8;
    int v[8];
#pragma unroll
    for (int k = 0; k < 8; k++) { int i = base + k; v[k] = (i < N) ? g_cnt[i] : 0; }
    int tot = 0;
#pragma unroll
    for (int k = 0; k < 8; k++) { int t = v[k]; v[k] = tot; tot += t; }

    int x = tot;
#pragma unroll
    for (int d = 1; d < 32; d <<= 1) {
        int y = __shfl_up_sync(FULL, x, d);
        if (lane >= d) x += y;
    }
    if (lane == 31) wsum[wid] = x;
    __syncthreads();
    if (wid == 0) {
        int w = (lane < 16) ? wsum[lane] : 0;
#pragma unroll
        for (int d = 1; d < 32; d <<= 1) {
            int y = __shfl_up_sync(FULL, w, d);
            if (lane >= d) w += y;
        }
        if (lane < 16) wsum[lane] = w;
    }
    __syncthreads();
    int toff = x - tot + ((wid > 0) ? wsum[wid - 1] : 0) + blk_base;
#pragma unroll
    for (int k = 0; k < 8; k++) {
        int i = base + k;
        if (i < N) { int e = toff + v[k]; g_row_off[i] = e; g_cursor[i] = e; }
    }
}

__global__ void scatter_kernel(const int* __restrict__ src,
                               const int* __restrict__ dst, int E) {
    int i = (blockIdx.x * blockDim.x + threadIdx.x) * 4;
    if (i + 4 <= E) {
        int4 s = __ldcs((const int4*)(src + i));
        int4 d = __ldcs((const int4*)(dst + i));
        g_csr_src[atomicAdd(&g_cursor[d.x], 1)] = s.x;
        g_csr_src[atomicAdd(&g_cursor[d.y], 1)] = s.y;
        g_csr_src[atomicAdd(&g_cursor[d.z], 1)] = s.z;
        g_csr_src[atomicAdd(&g_cursor[d.w], 1)] = s.w;
    } else {
        for (int k = i; k < E; k++)
            g_csr_src[atomicAdd(&g_cursor[dst[k]], 1)] = src[k];
    }
}

// ---------------- 3) single-pass pipelined softmax + fp16 aggregation ----------------
// one warp per node, 8-edge unrolled. Each lane computes coefficients for head
// (lane&7) on edges q=lane>>3 and q+4; iteration j+8's coefs computed while
// iteration j's 8 gathers are in flight.
__global__ void __launch_bounds__(256) gat_agg_kernel(const float* __restrict__ bias,
                                                      float* __restrict__ out, int N) {
    int gwarp = (blockIdx.x * blockDim.x + threadIdx.x) >> 5;
    int lane = threadIdx.x & 31;
    if (gwarp >= N) return;

    const int n = gwarp;
    const int base = g_row_off[n];
    const int deg = g_row_off[n + 1] - base;

    float* orow = out + (size_t)n * HF;
    const float4* b4 = (const float4*)bias;
    float4 bv0 = b4[lane * 2], bv1 = b4[lane * 2 + 1];

    if (deg == 0) {
        __stcs((float4*)orow + lane * 2, bv0);
        __stcs((float4*)orow + lane * 2 + 1, bv1);
        return;
    }

    const int lane7 = lane & 7;
    const int hh = lane & 7;          // coef-role head
    const int q = lane >> 3;          // coef-role edge (q and q+4)
    const int gh = lane >> 2;         // gather-role head
    const float er_h = __ldg(g_er + (size_t)n * HEADS + hh);

    float acc[8];
#pragma unroll
    for (int j = 0; j < 8; j++) acc[j] = 0.f;
    float smp = 0.f;

    // prologue: indices + coefficients for first 8-edge group
    int sj_c;
    {
        int i8 = lane7;
        sj_c = __ldcs(g_csr_src + base + ((i8 < deg) ? i8 : (deg - 1)));
    }
    float ca_c, cb_c;
    {
        int sqa = __shfl_sync(FULL, sj_c, q);
        int sqb = __shfl_sync(FULL, sj_c, q + 4);
        float ea = __ldg(g_el + (size_t)sqa * HEADS + hh) + er_h;
        float eb = __ldg(g_el + (size_t)sqb * HEADS + hh) + er_h;
        ea = (ea > 0.f) ? ea : NEG_SLOPE * ea;
        eb = (eb > 0.f) ? eb : NEG_SLOPE * eb;
        ca_c = (q < deg) ? __expf(ea) : 0.f;
        cb_c = ((q + 4) < deg) ? __expf(eb) : 0.f;
    }

    for (int j = 0; j < deg; j += 8) {
        const int jn = j + 8;
        const bool more = jn < deg;

        // A) prefetch next group's csr indices
        int sj_n = 0;
        if (more) {
            int i8 = jn + lane7;
            sj_n = __ldcs(g_csr_src + base + ((i8 < deg) ? i8 : (deg - 1)));
        }

        // B) broadcast current indices + coefficients
        int s0 = __shfl_sync(FULL, sj_c, 0);
        int s1 = __shfl_sync(FULL, sj_c, 1);
        int s2 = __shfl_sync(FULL, sj_c, 2);
        int s3 = __shfl_sync(FULL, sj_c, 3);
        int s4 = __shfl_sync(FULL, sj_c, 4);
        int s5 = __shfl_sync(FULL, sj_c, 5);
        int s6 = __shfl_sync(FULL, sj_c, 6);
        int s7 = __shfl_sync(FULL, sj_c, 7);
        float c0 = __shfl_sync(FULL, ca_c, gh);
        float c1 = __shfl_sync(FULL, ca_c, 8 + gh);
        float c2 = __shfl_sync(FULL, ca_c, 16 + gh);
        float c3 = __shfl_sync(FULL, ca_c, 24 + gh);
        float c4 = __shfl_sync(FULL, cb_c, gh);
        float c5 = __shfl_sync(FULL, cb_c, 8 + gh);
        float c6 = __shfl_sync(FULL, cb_c, 16 + gh);
        float c7 = __shfl_sync(FULL, cb_c, 24 + gh);
        smp += ca_c + cb_c;

        // C) issue 8 independent fp16 gathers
        uint4 w0 = *((const uint4*)(g_hh + (size_t)s0 * HF) + lane);
        uint4 w1 = *((const uint4*)(g_hh + (size_t)s1 * HF) + lane);
        uint4 w2 = *((const uint4*)(g_hh + (size_t)s2 * HF) + lane);
        uint4 w3 = *((const uint4*)(g_hh + (size_t)s3 * HF) + lane);
        uint4 w4 = *((const uint4*)(g_hh + (size_t)s4 * HF) + lane);
        uint4 w5 = *((const uint4*)(g_hh + (size_t)s5 * HF) + lane);
        uint4 w6 = *((const uint4*)(g_hh + (size_t)s6 * HF) + lane);
        uint4 w7 = *((const uint4*)(g_hh + (size_t)s7 * HF) + lane);

        // D) compute NEXT coefficients while gathers are in flight
        float ca_n = 0.f, cb_n = 0.f;
        if (more) {
            int sqa = __shfl_sync(FULL, sj_n, q);
            int sqb = __shfl_sync(FULL, sj_n, q + 4);
            float ea = __ldg(g_el + (size_t)sqa * HEADS + hh) + er_h;
            float eb = __ldg(g_el + (size_t)sqb * HEADS + hh) + er_h;
            ea = (ea > 0.f) ? ea : NEG_SLOPE * ea;
            eb = (eb > 0.f) ? eb : NEG_SLOPE * eb;
            ca_n = ((jn + q) < deg) ? __expf(ea) : 0.f;
            cb_n = ((jn + q + 4) < deg) ? __expf(eb) : 0.f;
        }

        // E) convert + FMA (8 edges)
#define AGG_EDGE(W, C)                                                        \
        {                                                                     \
            float2 f0 = __half22float2(*(const __half2*)&(W).x);              \
            float2 f1 = __half22float2(*(const __half2*)&(W).y);              \
            float2 f2 = __half22float2(*(const __half2*)&(W).z);              \
            float2 f3 = __half22float2(*(const __half2*)&(W).w);              \
            acc[0] = fmaf(f0.x, (C), acc[0]); acc[1] = fmaf(f0.y, (C), acc[1]); \
            acc[2] = fmaf(f1.x, (C), acc[2]); acc[3] = fmaf(f1.y, (C), acc[3]); \
            acc[4] = fmaf(f2.x, (C), acc[4]); acc[5] = fmaf(f2.y, (C), acc[5]); \
            acc[6] = fmaf(f3.x, (C), acc[6]); acc[7] = fmaf(f3.y, (C), acc[7]); \
        }
        AGG_EDGE(w0, c0) AGG_EDGE(w1, c1) AGG_EDGE(w2, c2) AGG_EDGE(w3, c3)
        AGG_EDGE(w4, c4) AGG_EDGE(w5, c5) AGG_EDGE(w6, c6) AGG_EDGE(w7, c7)
#undef AGG_EDGE

        sj_c = sj_n;
        ca_c = ca_n;
        cb_c = cb_n;
    }

    // Σ exp: lanes {hh, hh+8, hh+16, hh+24} hold partials for head hh
    smp += __shfl_xor_sync(FULL, smp, 8);
    smp += __shfl_xor_sync(FULL, smp, 16);
    float inv = 1.0f / smp;
    float cinv = __shfl_sync(FULL, inv, gh);

    __stcs((float4*)orow + lane * 2,
           make_float4(fmaf(acc[0], cinv, bv0.x), fmaf(acc[1], cinv, bv0.y),
                       fmaf(acc[2], cinv, bv0.z), fmaf(acc[3], cinv, bv0.w)));
    __stcs((float4*)orow + lane * 2 + 1,
           make_float4(fmaf(acc[4], cinv, bv1.x), fmaf(acc[5], cinv, bv1.y),
                       fmaf(acc[6], cinv, bv1.z), fmaf(acc[7], cinv, bv1.w)));
}

// ---------------- launch (fork-join: CSR build overlaps GEMM) ----------------
static cudaStream_t get_side_stream() {
    static cudaStream_t s = [] {
        cudaStream_t t;
        cudaStreamCreateWithFlags(&t, cudaStreamNonBlocking);
        return t;
    }();
    return s;
}
static cudaEvent_t get_ev(int which) {
    static cudaEvent_t e0 = [] {
        cudaEvent_t e; cudaEventCreateWithFlags(&e, cudaEventDisableTiming); return e;
    }();
    static cudaEvent_t e1 = [] {
        cudaEvent_t e; cudaEventCreateWithFlags(&e, cudaEventDisableTiming); return e;
    }();
    return which ? e1 : e0;
}

extern "C" void kernel_launch(void* const* d_in, const int* in_sizes, int n_in,
                              void* d_out, int out_size) {
    const float* feat   = (const float*)d_in[0];
    const int*   src    = (const int*)d_in[1];
    const int*   dst    = (const int*)d_in[2];
    const float* fc_w   = (const float*)d_in[3];
    const float* attn_l = (const float*)d_in[4];
    const float* attn_r = (const float*)d_in[5];
    const float* bias   = (const float*)d_in[6];
    float* out = (float*)d_out;

    const int M = in_sizes[0] / IN_FEATS;
    const int E = in_sizes[1];

    cudaFuncSetAttribute(gemm_wmma_kernel,
                         cudaFuncAttributeMaxDynamicSharedMemorySize, GEMM_SMEM_BYTES);

    cudaStream_t sB = get_side_stream();
    cudaEvent_t evF = get_ev(0), evJ = get_ev(1);

    cudaEventRecord(evF, 0);
    cudaStreamWaitEvent(sB, evF, 0);

    // side stream: CSR build
    zero_cnt_kernel<<<(M + 255) / 256, 256, 0, sB>>>(M);
    hist_kernel<<<(E / 4 + 255) / 256, 256, 0, sB>>>(dst, E);
    int nb = (M + SCAN_CHUNK - 1) / SCAN_CHUNK;
    partial_sum_kernel<<<nb, 512, 0, sB>>>(M);
    scan_blk_kernel<<<1, 32, 0, sB>>>(nb, E, M);
    scan_final_kernel<<<nb, 512, 0, sB>>>(M);
    scatter_kernel<<<(E / 4 + 255) / 256, 256, 0, sB>>>(src, dst, E);

    // main stream: weight convert + fused-conversion tensor-core GEMM (+ el/er)
    cvt_w_kernel<<<(HF * IN_FEATS / 8) / 256, 256>>>(fc_w);
    gemm_wmma_kernel<<<(M + 63) / 64, 256, GEMM_SMEM_BYTES>>>(feat, attn_l, attn_r, M);

    cudaEventRecord(evJ, sB);
    cudaStreamWaitEvent(0, evJ, 0);

    int warp_blocks = (M * 32 + 255) / 256;
    gat_agg_kernel<<<warp_blocks, 256>>>(bias, out, M);
}